// round 1
// baseline (speedup 1.0000x reference)
#include <cuda_runtime.h>

// Problem constants
#define NB 8
#define NT 2048
#define NC 1024
#define NH 64
#define NM (NB * NT)   // 16384 rows

// Scratch for projected q, k, v ([B*T, H] each). __device__ globals are the
// sanctioned way to get scratch under the allocation guards.
__device__ float g_q[NM * NH];
__device__ float g_k[NM * NH];
__device__ float g_v[NM * NH];

// ---------------------------------------------------------------------------
// Kernel 1: QKV projection.  out[m, h] = sum_k x[m, k] * W[h, k]
// Register-blocked SGEMM: BM=128, BN=64(=H), BK=16, 256 threads, 8x4 micro.
// blockIdx.y selects which of the three weight matrices / outputs.
// ---------------------------------------------------------------------------
__global__ __launch_bounds__(256) void qkv_gemm_kernel(
    const float* __restrict__ x,
    const float* __restrict__ Wq,
    const float* __restrict__ Wk,
    const float* __restrict__ Wv)
{
    __shared__ float As[16][132];  // [BK][BM+4]  (x tile, transposed)
    __shared__ float Bs[16][68];   // [BK][BN+4]  (W tile, transposed)

    const float* W;
    float* out;
    if (blockIdx.y == 0)      { W = Wq; out = g_q; }
    else if (blockIdx.y == 1) { W = Wk; out = g_k; }
    else                      { W = Wv; out = g_v; }

    const int row0 = blockIdx.x * 128;
    const int tid  = threadIdx.x;
    const int tm   = tid >> 4;   // 0..15 -> owns 8 rows
    const int tn   = tid & 15;   // 0..15 -> owns 4 cols

    float acc[8][4];
#pragma unroll
    for (int i = 0; i < 8; i++)
#pragma unroll
        for (int j = 0; j < 4; j++) acc[i][j] = 0.f;

    for (int kt = 0; kt < NC; kt += 16) {
        // Load x tile: 128 rows x 16 k = 512 float4, 2 per thread.
#pragma unroll
        for (int l = 0; l < 2; l++) {
            int i  = tid + l * 256;
            int r  = i >> 2;             // 0..127
            int k4 = (i & 3) * 4;        // 0,4,8,12
            float4 v4 = *(const float4*)(x + (size_t)(row0 + r) * NC + kt + k4);
            As[k4 + 0][r] = v4.x;
            As[k4 + 1][r] = v4.y;
            As[k4 + 2][r] = v4.z;
            As[k4 + 3][r] = v4.w;
        }
        // Load W tile: 64 rows x 16 k = 256 float4, 1 per thread.
        {
            int r  = tid >> 2;           // 0..63
            int k4 = (tid & 3) * 4;
            float4 v4 = *(const float4*)(W + (size_t)r * NC + kt + k4);
            Bs[k4 + 0][r] = v4.x;
            Bs[k4 + 1][r] = v4.y;
            Bs[k4 + 2][r] = v4.z;
            Bs[k4 + 3][r] = v4.w;
        }
        __syncthreads();

#pragma unroll
        for (int kk = 0; kk < 16; kk++) {
            float4 a0 = *(const float4*)&As[kk][tm * 8];
            float4 a1 = *(const float4*)&As[kk][tm * 8 + 4];
            float4 bv = *(const float4*)&Bs[kk][tn * 4];
            float a[8] = {a0.x, a0.y, a0.z, a0.w, a1.x, a1.y, a1.z, a1.w};
            float b[4] = {bv.x, bv.y, bv.z, bv.w};
#pragma unroll
            for (int i = 0; i < 8; i++)
#pragma unroll
                for (int j = 0; j < 4; j++)
                    acc[i][j] += a[i] * b[j];
        }
        __syncthreads();
    }

#pragma unroll
    for (int i = 0; i < 8; i++) {
        float4 o = make_float4(acc[i][0], acc[i][1], acc[i][2], acc[i][3]);
        *(float4*)(out + (size_t)(row0 + tm * 8 + i) * NH + tn * 4) = o;
    }
}

// ---------------------------------------------------------------------------
// Kernel 2: causal flash attention, fp32.
// Grid (T/64, B), 256 threads, 64x64 tiles, online softmax in base 2.
// Smem: Qt[h][r], Kt[h][c] (transposed so the S-GEMM inner loop reads
// contiguous float4), Vs[c][h], Ss[r][c], plus m/l/corr rows.
// ---------------------------------------------------------------------------
#define SPAD 68
#define ATTN_SMEM_FLOATS (4 * 64 * SPAD + 3 * 64)
#define ATTN_SMEM_BYTES  (ATTN_SMEM_FLOATS * 4)

__global__ __launch_bounds__(256) void attn_kernel(float* __restrict__ out)
{
    extern __shared__ float sm[];
    float* Qt   = sm;                  // [64][SPAD]  (h, r)
    float* Kt   = Qt + 64 * SPAD;      // [64][SPAD]  (h, c)
    float* Vs   = Kt + 64 * SPAD;      // [64][SPAD]  (c, h)
    float* Ss   = Vs + 64 * SPAD;      // [64][SPAD]  (r, c)
    float* mrow = Ss + 64 * SPAD;      // [64]
    float* lrow = mrow + 64;           // [64]
    float* crow = lrow + 64;           // [64]

    const int b    = blockIdx.y;
    const int qi   = blockIdx.x;
    const int row0 = qi * 64;
    const float* qp = g_q + (size_t)b * NT * NH;
    const float* kp = g_k + (size_t)b * NT * NH;
    const float* vp = g_v + (size_t)b * NT * NH;

    const int tid = threadIdx.x;
    const int tm  = tid >> 4;   // 0..15 -> 4 query rows
    const int tn  = tid & 15;   // 0..15 -> 4 cols

    // scale = log2(e) / sqrt(C): softmax done in base 2 via exp2f (MUFU EX2)
    const float scale = 1.4426950408889634f / 32.0f;

    // Load Q tile, transposed + pre-scaled.
    for (int i = tid; i < 64 * 16; i += 256) {
        int r  = i >> 4;
        int h4 = (i & 15) * 4;
        float4 v4 = *(const float4*)(qp + (size_t)(row0 + r) * NH + h4);
        Qt[(h4 + 0) * SPAD + r] = v4.x * scale;
        Qt[(h4 + 1) * SPAD + r] = v4.y * scale;
        Qt[(h4 + 2) * SPAD + r] = v4.z * scale;
        Qt[(h4 + 3) * SPAD + r] = v4.w * scale;
    }
    if (tid < 64) { mrow[tid] = -1e30f; lrow[tid] = 0.f; }

    float acc[4][4];
#pragma unroll
    for (int i = 0; i < 4; i++)
#pragma unroll
        for (int j = 0; j < 4; j++) acc[i][j] = 0.f;

    __syncthreads();

    for (int kj = 0; kj <= qi; kj++) {
        const int col0 = kj * 64;

        // Load K (transposed) and V (row-major) tiles.
        for (int i = tid; i < 64 * 16; i += 256) {
            int r  = i >> 4;
            int h4 = (i & 15) * 4;
            float4 v4 = *(const float4*)(kp + (size_t)(col0 + r) * NH + h4);
            Kt[(h4 + 0) * SPAD + r] = v4.x;
            Kt[(h4 + 1) * SPAD + r] = v4.y;
            Kt[(h4 + 2) * SPAD + r] = v4.z;
            Kt[(h4 + 3) * SPAD + r] = v4.w;
            float4 w4 = *(const float4*)(vp + (size_t)(col0 + r) * NH + h4);
            *(float4*)(Vs + r * SPAD + h4) = w4;
        }
        __syncthreads();

        // S = (scaled Q) . K^T  over h
        float s[4][4];
#pragma unroll
        for (int i = 0; i < 4; i++)
#pragma unroll
            for (int j = 0; j < 4; j++) s[i][j] = 0.f;

#pragma unroll
        for (int h = 0; h < 64; h++) {
            float4 a = *(const float4*)(Qt + h * SPAD + tm * 4);
            float4 bq = *(const float4*)(Kt + h * SPAD + tn * 4);
            float av[4] = {a.x, a.y, a.z, a.w};
            float bv[4] = {bq.x, bq.y, bq.z, bq.w};
#pragma unroll
            for (int i = 0; i < 4; i++)
#pragma unroll
                for (int j = 0; j < 4; j++)
                    s[i][j] += av[i] * bv[j];
        }

        // Causal mask (only the diagonal tile needs it) + store S.
        const bool diag = (kj == qi);
#pragma unroll
        for (int i = 0; i < 4; i++) {
#pragma unroll
            for (int j = 0; j < 4; j++) {
                int r = tm * 4 + i;
                int c = tn * 4 + j;
                float v = s[i][j];
                if (diag && c > r) v = -1e30f;
                Ss[r * SPAD + c] = v;
            }
        }
        __syncthreads();

        // Online softmax: one thread per row.
        if (tid < 64) {
            const int r = tid;
            float mOld = mrow[r];
            float mx = mOld;
#pragma unroll 8
            for (int c = 0; c < 64; c++) mx = fmaxf(mx, Ss[r * SPAD + c]);
            float corr = exp2f(mOld - mx);
            float sum = 0.f;
#pragma unroll 8
            for (int c = 0; c < 64; c++) {
                float p = exp2f(Ss[r * SPAD + c] - mx);
                Ss[r * SPAD + c] = p;
                sum += p;
            }
            lrow[r] = lrow[r] * corr + sum;
            mrow[r] = mx;
            crow[r] = corr;
        }
        __syncthreads();

        // Rescale accumulator, then O += P . V
        float cr[4];
#pragma unroll
        for (int i = 0; i < 4; i++) cr[i] = crow[tm * 4 + i];
#pragma unroll
        for (int i = 0; i < 4; i++)
#pragma unroll
            for (int j = 0; j < 4; j++) acc[i][j] *= cr[i];

#pragma unroll
        for (int c = 0; c < 64; c++) {
            float4 vv = *(const float4*)(Vs + c * SPAD + tn * 4);
            float vb[4] = {vv.x, vv.y, vv.z, vv.w};
            float p[4];
#pragma unroll
            for (int i = 0; i < 4; i++) p[i] = Ss[(tm * 4 + i) * SPAD + c];
#pragma unroll
            for (int i = 0; i < 4; i++)
#pragma unroll
                for (int j = 0; j < 4; j++)
                    acc[i][j] += p[i] * vb[j];
        }
        __syncthreads();   // protect Kt/Vs/Ss before next iteration
    }

    // Finalize: divide by l and store [B, T, H].
    float inv[4];
#pragma unroll
    for (int i = 0; i < 4; i++) inv[i] = 1.f / lrow[tm * 4 + i];
#pragma unroll
    for (int i = 0; i < 4; i++) {
        float4 o = make_float4(acc[i][0] * inv[i], acc[i][1] * inv[i],
                               acc[i][2] * inv[i], acc[i][3] * inv[i]);
        size_t t = (size_t)b * NT + row0 + tm * 4 + i;
        *(float4*)(out + t * NH + tn * 4) = o;
    }
}

// ---------------------------------------------------------------------------
extern "C" void kernel_launch(void* const* d_in, const int* in_sizes, int n_in,
                              void* d_out, int out_size)
{
    (void)in_sizes; (void)n_in; (void)out_size;
    const float* x  = (const float*)d_in[0];
    const float* Wk = (const float*)d_in[1];
    const float* Wq = (const float*)d_in[2];
    const float* Wv = (const float*)d_in[3];
    float* out = (float*)d_out;

    // Non-enqueuing attribute set; safe under graph capture, idempotent.
    cudaFuncSetAttribute(attn_kernel,
                         cudaFuncAttributeMaxDynamicSharedMemorySize,
                         ATTN_SMEM_BYTES);

    qkv_gemm_kernel<<<dim3(NM / 128, 3), 256>>>(x, Wq, Wk, Wv);
    attn_kernel<<<dim3(NT / 64, NB), 256, ATTN_SMEM_BYTES>>>(out);
}

// round 4
// speedup vs baseline: 3.5278x; 3.5278x over previous
#include <cuda_runtime.h>
#include <cuda_bf16.h>
#include <cstdint>

// Problem constants
#define NB 8
#define NT 2048
#define NC 1024
#define NH 64
#define NM (NB * NT)   // 16384 rows

#define QSCALE (1.4426950408889634f / 32.0f)   // log2(e)/sqrt(C)

// Split-bf16 scratch: q (pre-scaled), k as [b][t][h]; v transposed [b][h][t].
__device__ __nv_bfloat16 g_qh[NM * NH];
__device__ __nv_bfloat16 g_ql[NM * NH];
__device__ __nv_bfloat16 g_kh[NM * NH];
__device__ __nv_bfloat16 g_kl[NM * NH];
__device__ __nv_bfloat16 g_vth[NB * NH * NT];
__device__ __nv_bfloat16 g_vtl[NB * NH * NT];

// ===========================================================================
// Helpers (baseline PTX only: ldmatrix / mma.sync / cp.async — NO tcgen05)
// ===========================================================================
__device__ __forceinline__ uint32_t smem_u32(const void* p) {
    uint32_t a;
    asm("{ .reg .u64 t; cvta.to.shared.u64 t, %1; cvt.u32.u64 %0, t; }"
        : "=r"(a) : "l"(p));
    return a;
}

__device__ __forceinline__ void ldsm4(uint32_t addr, uint32_t& r0, uint32_t& r1,
                                      uint32_t& r2, uint32_t& r3) {
    asm volatile("ldmatrix.sync.aligned.m8n8.x4.shared.b16 {%0,%1,%2,%3}, [%4];\n"
                 : "=r"(r0), "=r"(r1), "=r"(r2), "=r"(r3) : "r"(addr));
}

// D(+=) A(16x16 bf16) * B(16x8 bf16), fp32 accum, in-place C
__device__ __forceinline__ void mma16816(float* d, const uint32_t* a,
                                         uint32_t b0, uint32_t b1) {
    asm volatile(
        "mma.sync.aligned.m16n8k16.row.col.f32.bf16.bf16.f32 "
        "{%0,%1,%2,%3}, {%4,%5,%6,%7}, {%8,%9}, {%0,%1,%2,%3};\n"
        : "+f"(d[0]), "+f"(d[1]), "+f"(d[2]), "+f"(d[3])
        : "r"(a[0]), "r"(a[1]), "r"(a[2]), "r"(a[3]), "r"(b0), "r"(b1));
}

#define CP_ASYNC16(dst, src) \
    asm volatile("cp.async.cg.shared.global [%0], [%1], 16;\n" :: "r"(dst), "l"(src))
#define CP_COMMIT() asm volatile("cp.async.commit_group;\n" ::: "memory")
#define CP_WAIT1()  asm volatile("cp.async.wait_group 1;\n" ::: "memory")
#define CP_WAIT0()  asm volatile("cp.async.wait_group 0;\n" ::: "memory")

// Split two fp32 into packed bf16x2 (hi) and packed bf16x2 (residual lo).
__device__ __forceinline__ void split2(float v0, float v1, uint32_t& hi, uint32_t& lo) {
    __nv_bfloat162 h = __floats2bfloat162_rn(v0, v1);
    float r0 = v0 - __bfloat162float(h.x);
    float r1 = v1 - __bfloat162float(h.y);
    __nv_bfloat162 l = __floats2bfloat162_rn(r0, r1);
    hi = *reinterpret_cast<uint32_t*>(&h);
    lo = *reinterpret_cast<uint32_t*>(&l);
}

// ===========================================================================
// Kernel 1: fused QKV projection, split-bf16 HMMA.
// out[m, c] for c in [0,192): 0-63 q (pre-scaled), 64-127 k, 128-191 v.
// Block: 128 rows x 192 cols, 8 warps (2x4), BK=32.
// ===========================================================================
// smem byte offsets (bf16 rows padded to 40 elems = 80 B for conflict-free ldsm)
#define P_AH 0
#define P_AL 10240
#define P_BH 20480
#define P_BL 35840
#define P_SMEM 51200

__global__ __launch_bounds__(256) void qkv_mma_kernel(
    const float* __restrict__ x,
    const float* __restrict__ Wq,
    const float* __restrict__ Wk,
    const float* __restrict__ Wv)
{
    extern __shared__ char smraw[];
    uint32_t sb = smem_u32(smraw);
    uint32_t* s32 = (uint32_t*)smraw;

    const int tid  = threadIdx.x;
    const int lane = tid & 31;
    const int wid  = tid >> 5;
    const int wm   = wid >> 2;      // 0..1 (row half)
    const int wn   = wid & 3;       // 0..3 (48-col slice)
    const int row0 = blockIdx.x * 128;

    // ldmatrix per-thread addressing components
    const int ar  = lane & 15;
    const int ak8 = (lane & 16) >> 1;              // +8 k if lane>=16
    const int bn  = (lane & 7) + ((lane & 16) >> 1);
    const int bk8 = ((lane >> 3) & 1) << 3;

    float acc[4][6][4];
#pragma unroll
    for (int i = 0; i < 4; i++)
#pragma unroll
        for (int j = 0; j < 6; j++)
#pragma unroll
            for (int q = 0; q < 4; q++) acc[i][j][q] = 0.f;

    float4 ra[4], rb[6];
    // initial global loads (kt = 0)
#pragma unroll
    for (int l = 0; l < 4; l++) {
        int idx = tid + l * 256, r = idx >> 3, k4 = (idx & 7) << 2;
        ra[l] = *(const float4*)(x + (size_t)(row0 + r) * NC + k4);
    }
#pragma unroll
    for (int l = 0; l < 6; l++) {
        int idx = tid + l * 256, r = idx >> 3, k4 = (idx & 7) << 2;
        const float* W = (r < 64) ? Wq : (r < 128) ? Wk : Wv;
        rb[l] = *(const float4*)(W + (size_t)(r & 63) * NC + k4);
    }

    for (int kt = 0; kt < NC; kt += 32) {
        __syncthreads();   // previous mma done before smem overwrite
        // convert + store tile
#pragma unroll
        for (int l = 0; l < 4; l++) {
            int idx = tid + l * 256, r = idx >> 3, k4 = (idx & 7) << 2;
            uint32_t h0, l0, h1, l1;
            split2(ra[l].x, ra[l].y, h0, l0);
            split2(ra[l].z, ra[l].w, h1, l1);
            int o = r * 20 + (k4 >> 1);
            s32[(P_AH >> 2) + o] = h0; s32[(P_AH >> 2) + o + 1] = h1;
            s32[(P_AL >> 2) + o] = l0; s32[(P_AL >> 2) + o + 1] = l1;
        }
#pragma unroll
        for (int l = 0; l < 6; l++) {
            int idx = tid + l * 256, r = idx >> 3, k4 = (idx & 7) << 2;
            uint32_t h0, l0, h1, l1;
            split2(rb[l].x, rb[l].y, h0, l0);
            split2(rb[l].z, rb[l].w, h1, l1);
            int o = r * 20 + (k4 >> 1);
            s32[(P_BH >> 2) + o] = h0; s32[(P_BH >> 2) + o + 1] = h1;
            s32[(P_BL >> 2) + o] = l0; s32[(P_BL >> 2) + o + 1] = l1;
        }
        __syncthreads();

        // prefetch next tile (latency overlaps mma below)
        if (kt + 32 < NC) {
            int kn = kt + 32;
#pragma unroll
            for (int l = 0; l < 4; l++) {
                int idx = tid + l * 256, r = idx >> 3, k4 = (idx & 7) << 2;
                ra[l] = *(const float4*)(x + (size_t)(row0 + r) * NC + kn + k4);
            }
#pragma unroll
            for (int l = 0; l < 6; l++) {
                int idx = tid + l * 256, r = idx >> 3, k4 = (idx & 7) << 2;
                const float* W = (r < 64) ? Wq : (r < 128) ? Wk : Wv;
                rb[l] = *(const float4*)(W + (size_t)(r & 63) * NC + kn + k4);
            }
        }

        // MMA: 2 k16 steps
#pragma unroll
        for (int ks = 0; ks < 2; ks++) {
            const int kb = ks * 16;
            uint32_t bh[12], bl[12];
#pragma unroll
            for (int jp = 0; jp < 3; jp++) {
                int n0 = wn * 48 + jp * 16;
                uint32_t off = (uint32_t)(n0 + bn) * 80 + (uint32_t)(kb + bk8) * 2;
                ldsm4(sb + P_BH + off, bh[4*jp], bh[4*jp+1], bh[4*jp+2], bh[4*jp+3]);
                ldsm4(sb + P_BL + off, bl[4*jp], bl[4*jp+1], bl[4*jp+2], bl[4*jp+3]);
            }
#pragma unroll
            for (int mf = 0; mf < 4; mf++) {
                int r0l = wm * 64 + mf * 16;
                uint32_t aoff = (uint32_t)(r0l + ar) * 80 + (uint32_t)(kb + ak8) * 2;
                uint32_t ah[4], al[4];
                ldsm4(sb + P_AH + aoff, ah[0], ah[1], ah[2], ah[3]);
                ldsm4(sb + P_AL + aoff, al[0], al[1], al[2], al[3]);
#pragma unroll
                for (int nf = 0; nf < 6; nf++) {
                    mma16816(acc[mf][nf], ah, bh[2*nf], bh[2*nf+1]);
                    mma16816(acc[mf][nf], ah, bl[2*nf], bl[2*nf+1]);
                    mma16816(acc[mf][nf], al, bh[2*nf], bh[2*nf+1]);
                }
            }
        }
    }

    // ---- epilogue: split fp32 acc -> bf16 hi/lo scratch ----
    const int bq = row0 >> 11;   // batch index (2048 rows per batch)
#pragma unroll
    for (int mf = 0; mf < 4; mf++) {
        int rl = wm * 64 + mf * 16 + (lane >> 2);
        size_t r0 = (size_t)row0 + rl;
#pragma unroll
        for (int nf = 0; nf < 6; nf++) {
            int c = wn * 48 + nf * 8 + ((lane & 3) << 1);
            float v00 = acc[mf][nf][0], v01 = acc[mf][nf][1];
            float v10 = acc[mf][nf][2], v11 = acc[mf][nf][3];
            int mat = c >> 6, lc = c & 63;
            if (mat == 0) { v00 *= QSCALE; v01 *= QSCALE; v10 *= QSCALE; v11 *= QSCALE; }
            uint32_t h0, l0, h1, l1;
            split2(v00, v01, h0, l0);
            split2(v10, v11, h1, l1);
            if (mat == 0) {
                *(uint32_t*)&g_qh[r0 * NH + lc]       = h0;
                *(uint32_t*)&g_qh[(r0 + 8) * NH + lc] = h1;
                *(uint32_t*)&g_ql[r0 * NH + lc]       = l0;
                *(uint32_t*)&g_ql[(r0 + 8) * NH + lc] = l1;
            } else if (mat == 1) {
                *(uint32_t*)&g_kh[r0 * NH + lc]       = h0;
                *(uint32_t*)&g_kh[(r0 + 8) * NH + lc] = h1;
                *(uint32_t*)&g_kl[r0 * NH + lc]       = l0;
                *(uint32_t*)&g_kl[(r0 + 8) * NH + lc] = l1;
            } else {
                // v transposed: g_vt[b][h][t]
                __nv_bfloat162 H0 = *(__nv_bfloat162*)&h0;
                __nv_bfloat162 H1 = *(__nv_bfloat162*)&h1;
                __nv_bfloat162 L0 = *(__nv_bfloat162*)&l0;
                __nv_bfloat162 L1 = *(__nv_bfloat162*)&l1;
                size_t t0 = r0 & 2047;
                size_t base = ((size_t)bq * NH + lc) * NT + t0;
                g_vth[base]          = H0.x;  g_vth[base + 8]      = H1.x;
                g_vth[base + NT]     = H0.y;  g_vth[base + NT + 8] = H1.y;
                g_vtl[base]          = L0.x;  g_vtl[base + 8]      = L1.x;
                g_vtl[base + NT]     = L0.y;  g_vtl[base + NT + 8] = L1.y;
            }
        }
    }
}

// ===========================================================================
// Kernel 2: flash attention, split-bf16 HMMA, register-resident softmax.
// BQ=64, 4 warps x 16 rows; KV tiles of 64 double-buffered via cp.async.
// Mirrored causal schedule: block bx does q-tiles {bx, 31-bx} (33 iters).
// ===========================================================================
// smem: rows padded to 72 bf16 = 144 B
#define A_QH   0
#define A_QL   9216
#define A_KV   18432
#define A_TILE 9216
#define A_SMEM (A_KV + 8 * A_TILE)   // 92160

__device__ __forceinline__ void issue_q(uint32_t sb, int b, int q0, int tid) {
#pragma unroll
    for (int l = 0; l < 8; l++) {
        int idx = tid + l * 128;
        int part = idx >> 9, rem = idx & 511, r = rem >> 3, s = rem & 7;
        const __nv_bfloat16* src =
            (part ? g_ql : g_qh) + ((size_t)(b * NT + q0 + r) * NH + s * 8);
        uint32_t dst = sb + (part ? A_QL : A_QH) + (uint32_t)r * 144 + s * 16;
        CP_ASYNC16(dst, src);
    }
}

__device__ __forceinline__ void issue_kv(uint32_t sb, int b, int c0, int buf, int tid) {
#pragma unroll
    for (int l = 0; l < 16; l++) {
        int idx = tid + l * 128;
        int w = idx >> 9, rem = idx & 511, r = rem >> 3, s = rem & 7;
        const __nv_bfloat16* src;
        if (w == 0)      src = g_kh  + ((size_t)(b * NT + c0 + r) * NH + s * 8);
        else if (w == 1) src = g_kl  + ((size_t)(b * NT + c0 + r) * NH + s * 8);
        else if (w == 2) src = g_vth + ((size_t)(b * NH + r) * NT + c0 + s * 8);
        else             src = g_vtl + ((size_t)(b * NH + r) * NT + c0 + s * 8);
        uint32_t dst = sb + A_KV + (uint32_t)(buf * 4 + w) * A_TILE
                       + (uint32_t)r * 144 + s * 16;
        CP_ASYNC16(dst, src);
    }
}

__global__ __launch_bounds__(128) void attn_mma_kernel(float* __restrict__ out)
{
    extern __shared__ char smraw[];
    uint32_t sb = smem_u32(smraw);
    const int tid  = threadIdx.x;
    const int lane = tid & 31;
    const int warp = tid >> 5;
    const int b    = blockIdx.y;
    const int w16  = warp * 16;

    const int ar  = lane & 15;
    const int ak8 = (lane & 16) >> 1;
    const int bn  = (lane & 7) + ((lane & 16) >> 1);
    const int bk8 = ((lane >> 3) & 1) << 3;
    const uint32_t boff = (uint32_t)bn * 144 + (uint32_t)bk8 * 2;

    for (int pass = 0; pass < 2; pass++) {
        const int qi = pass ? (31 - blockIdx.x) : blockIdx.x;
        const int q0 = qi * 64;

        issue_q(sb, b, q0, tid);  CP_COMMIT();
        issue_kv(sb, b, 0, 0, tid); CP_COMMIT();
        CP_WAIT1();               // Q group complete
        __syncthreads();

        // Q fragments, resident for the whole pass
        uint32_t qfh[16], qfl[16];
#pragma unroll
        for (int ks = 0; ks < 4; ks++) {
            uint32_t a = sb + A_QH + (uint32_t)(w16 + ar) * 144
                         + (uint32_t)(ks * 16 + ak8) * 2;
            ldsm4(a,        qfh[ks*4], qfh[ks*4+1], qfh[ks*4+2], qfh[ks*4+3]);
            ldsm4(a + 9216, qfl[ks*4], qfl[ks*4+1], qfl[ks*4+2], qfl[ks*4+3]);
        }

        float m0 = -1e30f, m1 = -1e30f, l0s = 0.f, l1s = 0.f;
        float o[8][4];
#pragma unroll
        for (int i = 0; i < 8; i++)
#pragma unroll
            for (int j = 0; j < 4; j++) o[i][j] = 0.f;

        for (int kj = 0; kj <= qi; kj++) {
            if (kj < qi) {
                issue_kv(sb, b, (kj + 1) * 64, (kj + 1) & 1, tid);
                CP_COMMIT();
                CP_WAIT1();
            } else {
                CP_WAIT0();
            }
            __syncthreads();

            const uint32_t khb = sb + A_KV + (uint32_t)((kj & 1) * 4 + 0) * A_TILE;
            const uint32_t klb = khb + A_TILE;
            const uint32_t vhb = khb + 2 * A_TILE;
            const uint32_t vlb = khb + 3 * A_TILE;

            // ---- S = Qs . K^T (3-term split) ----
            float s[8][4];
#pragma unroll
            for (int i = 0; i < 8; i++)
#pragma unroll
                for (int j = 0; j < 4; j++) s[i][j] = 0.f;

#pragma unroll
            for (int ks = 0; ks < 4; ks++) {
                const uint32_t* qh = &qfh[ks * 4];
                const uint32_t* ql = &qfl[ks * 4];
#pragma unroll
                for (int p = 0; p < 4; p++) {
                    uint32_t off = (uint32_t)(p * 16) * 144 + (uint32_t)(ks * 16) * 2 + boff;
                    uint32_t h0, h1, h2, h3, e0, e1, e2, e3;
                    ldsm4(khb + off, h0, h1, h2, h3);
                    ldsm4(klb + off, e0, e1, e2, e3);
                    mma16816(s[2*p],   qh, h0, h1);
                    mma16816(s[2*p],   qh, e0, e1);
                    mma16816(s[2*p],   ql, h0, h1);
                    mma16816(s[2*p+1], qh, h2, h3);
                    mma16816(s[2*p+1], qh, e2, e3);
                    mma16816(s[2*p+1], ql, h2, h3);
                }
            }

            // ---- causal mask (diagonal tile only) ----
            if (kj == qi) {
                int rl0 = w16 + (lane >> 2);
#pragma unroll
                for (int nf = 0; nf < 8; nf++) {
                    int c = nf * 8 + ((lane & 3) << 1);
                    if (c     > rl0)     s[nf][0] = -1e30f;
                    if (c + 1 > rl0)     s[nf][1] = -1e30f;
                    if (c     > rl0 + 8) s[nf][2] = -1e30f;
                    if (c + 1 > rl0 + 8) s[nf][3] = -1e30f;
                }
            }

            // ---- online softmax (base 2; scale pre-folded into Q) ----
            float tm0 = -1e30f, tm1 = -1e30f;
#pragma unroll
            for (int nf = 0; nf < 8; nf++) {
                tm0 = fmaxf(tm0, fmaxf(s[nf][0], s[nf][1]));
                tm1 = fmaxf(tm1, fmaxf(s[nf][2], s[nf][3]));
            }
            tm0 = fmaxf(tm0, __shfl_xor_sync(0xffffffffu, tm0, 1));
            tm0 = fmaxf(tm0, __shfl_xor_sync(0xffffffffu, tm0, 2));
            tm1 = fmaxf(tm1, __shfl_xor_sync(0xffffffffu, tm1, 1));
            tm1 = fmaxf(tm1, __shfl_xor_sync(0xffffffffu, tm1, 2));
            float mn0 = fmaxf(m0, tm0), mn1 = fmaxf(m1, tm1);
            float c0 = exp2f(m0 - mn0), c1 = exp2f(m1 - mn1);
            m0 = mn0; m1 = mn1;
#pragma unroll
            for (int nf = 0; nf < 8; nf++) {
                o[nf][0] *= c0; o[nf][1] *= c0;
                o[nf][2] *= c1; o[nf][3] *= c1;
            }
            float ps0 = 0.f, ps1 = 0.f;
#pragma unroll
            for (int nf = 0; nf < 8; nf++) {
                s[nf][0] = exp2f(s[nf][0] - mn0);
                s[nf][1] = exp2f(s[nf][1] - mn0);
                s[nf][2] = exp2f(s[nf][2] - mn1);
                s[nf][3] = exp2f(s[nf][3] - mn1);
                ps0 += s[nf][0] + s[nf][1];
                ps1 += s[nf][2] + s[nf][3];
            }
            ps0 += __shfl_xor_sync(0xffffffffu, ps0, 1);
            ps0 += __shfl_xor_sync(0xffffffffu, ps0, 2);
            ps1 += __shfl_xor_sync(0xffffffffu, ps1, 1);
            ps1 += __shfl_xor_sync(0xffffffffu, ps1, 2);
            l0s = l0s * c0 + ps0;
            l1s = l1s * c1 + ps1;

            // ---- O += P . V (P repacked in registers as A-fragments) ----
#pragma unroll
            for (int ks = 0; ks < 4; ks++) {
                uint32_t ph[4], pl[4];
                split2(s[2*ks][0],   s[2*ks][1],   ph[0], pl[0]);
                split2(s[2*ks][2],   s[2*ks][3],   ph[1], pl[1]);
                split2(s[2*ks+1][0], s[2*ks+1][1], ph[2], pl[2]);
                split2(s[2*ks+1][2], s[2*ks+1][3], ph[3], pl[3]);
#pragma unroll
                for (int p = 0; p < 4; p++) {
                    uint32_t off = (uint32_t)(p * 16) * 144 + (uint32_t)(ks * 16) * 2 + boff;
                    uint32_t h0, h1, h2, h3, e0, e1, e2, e3;
                    ldsm4(vhb + off, h0, h1, h2, h3);
                    ldsm4(vlb + off, e0, e1, e2, e3);
                    mma16816(o[2*p],   ph, h0, h1);
                    mma16816(o[2*p],   ph, e0, e1);
                    mma16816(o[2*p],   pl, h0, h1);
                    mma16816(o[2*p+1], ph, h2, h3);
                    mma16816(o[2*p+1], ph, e2, e3);
                    mma16816(o[2*p+1], pl, h2, h3);
                }
            }
            __syncthreads();   // all warps done before buffer reuse
        }

        // ---- finalize & store ----
        float inv0 = 1.f / l0s, inv1 = 1.f / l1s;
        int t0 = q0 + w16 + (lane >> 2);
        size_t rowb = ((size_t)b * NT + t0) * NH;
#pragma unroll
        for (int nf = 0; nf < 8; nf++) {
            int h = nf * 8 + ((lane & 3) << 1);
            float2 f0 = make_float2(o[nf][0] * inv0, o[nf][1] * inv0);
            float2 f1 = make_float2(o[nf][2] * inv1, o[nf][3] * inv1);
            *(float2*)&out[rowb + h]          = f0;
            *(float2*)&out[rowb + 8 * NH + h] = f1;
        }
        __syncthreads();
    }
}

// ===========================================================================
extern "C" void kernel_launch(void* const* d_in, const int* in_sizes, int n_in,
                              void* d_out, int out_size)
{
    (void)in_sizes; (void)n_in; (void)out_size;
    const float* x  = (const float*)d_in[0];
    const float* Wk = (const float*)d_in[1];
    const float* Wq = (const float*)d_in[2];
    const float* Wv = (const float*)d_in[3];
    float* out = (float*)d_out;

    cudaFuncSetAttribute(qkv_mma_kernel,
                         cudaFuncAttributeMaxDynamicSharedMemorySize, P_SMEM);
    cudaFuncSetAttribute(attn_mma_kernel,
                         cudaFuncAttributeMaxDynamicSharedMemorySize, A_SMEM);

    qkv_mma_kernel<<<NM / 128, 256, P_SMEM>>>(x, Wq, Wk, Wv);
    attn_mma_kernel<<<dim3(16, NB), 128, A_SMEM>>>(out);
}

// round 5
// speedup vs baseline: 3.5633x; 1.0101x over previous
#include <cuda_runtime.h>
#include <cuda_bf16.h>
#include <cstdint>

// Problem constants
#define NB 8
#define NT 2048
#define NC 1024
#define NH 64
#define NM (NB * NT)   // 16384 rows

#define QSCALE (1.4426950408889634f / 32.0f)   // log2(e)/sqrt(C)

// Split-bf16 scratch: q (pre-scaled), k as [b][t][h]; v transposed [b][h][t].
__device__ __nv_bfloat16 g_qh[NM * NH];
__device__ __nv_bfloat16 g_ql[NM * NH];
__device__ __nv_bfloat16 g_kh[NM * NH];
__device__ __nv_bfloat16 g_kl[NM * NH];
__device__ __nv_bfloat16 g_vth[NB * NH * NT];
__device__ __nv_bfloat16 g_vtl[NB * NH * NT];

// ===========================================================================
// Helpers (baseline PTX only: ldmatrix / mma.sync / cp.async — NO tcgen05)
// ===========================================================================
__device__ __forceinline__ uint32_t smem_u32(const void* p) {
    uint32_t a;
    asm("{ .reg .u64 t; cvta.to.shared.u64 t, %1; cvt.u32.u64 %0, t; }"
        : "=r"(a) : "l"(p));
    return a;
}

__device__ __forceinline__ void ldsm4(uint32_t addr, uint32_t& r0, uint32_t& r1,
                                      uint32_t& r2, uint32_t& r3) {
    asm volatile("ldmatrix.sync.aligned.m8n8.x4.shared.b16 {%0,%1,%2,%3}, [%4];\n"
                 : "=r"(r0), "=r"(r1), "=r"(r2), "=r"(r3) : "r"(addr));
}

// D(+=) A(16x16 bf16) * B(16x8 bf16), fp32 accum, in-place C
__device__ __forceinline__ void mma16816(float* d, const uint32_t* a,
                                         uint32_t b0, uint32_t b1) {
    asm volatile(
        "mma.sync.aligned.m16n8k16.row.col.f32.bf16.bf16.f32 "
        "{%0,%1,%2,%3}, {%4,%5,%6,%7}, {%8,%9}, {%0,%1,%2,%3};\n"
        : "+f"(d[0]), "+f"(d[1]), "+f"(d[2]), "+f"(d[3])
        : "r"(a[0]), "r"(a[1]), "r"(a[2]), "r"(a[3]), "r"(b0), "r"(b1));
}

#define CP_ASYNC16(dst, src) \
    asm volatile("cp.async.cg.shared.global [%0], [%1], 16;\n" :: "r"(dst), "l"(src))
#define CP_COMMIT() asm volatile("cp.async.commit_group;\n" ::: "memory")
#define CP_WAIT1()  asm volatile("cp.async.wait_group 1;\n" ::: "memory")
#define CP_WAIT0()  asm volatile("cp.async.wait_group 0;\n" ::: "memory")

// Split two fp32 into packed bf16x2 (hi) and packed bf16x2 (residual lo).
__device__ __forceinline__ void split2(float v0, float v1, uint32_t& hi, uint32_t& lo) {
    __nv_bfloat162 h = __floats2bfloat162_rn(v0, v1);
    float r0 = v0 - __bfloat162float(h.x);
    float r1 = v1 - __bfloat162float(h.y);
    __nv_bfloat162 l = __floats2bfloat162_rn(r0, r1);
    hi = *reinterpret_cast<uint32_t*>(&h);
    lo = *reinterpret_cast<uint32_t*>(&l);
}

// ===========================================================================
// Kernel 1: fused QKV projection, split-bf16 HMMA.
// out[m, c] for c in [0,192): 0-63 q (pre-scaled), 64-127 k, 128-191 v.
// Block: 128 rows x 192 cols, 8 warps (2x4), BK=32.
// ===========================================================================
// smem byte offsets (bf16 rows padded to 40 elems = 80 B for conflict-free ldsm)
#define P_AH 0
#define P_AL 10240
#define P_BH 20480
#define P_BL 35840
#define P_SMEM 51200

__global__ __launch_bounds__(256) void qkv_mma_kernel(
    const float* __restrict__ x,
    const float* __restrict__ Wq,
    const float* __restrict__ Wk,
    const float* __restrict__ Wv)
{
    extern __shared__ char smraw[];
    uint32_t sb = smem_u32(smraw);
    uint32_t* s32 = (uint32_t*)smraw;

    const int tid  = threadIdx.x;
    const int lane = tid & 31;
    const int wid  = tid >> 5;
    const int wm   = wid >> 2;      // 0..1 (row half)
    const int wn   = wid & 3;       // 0..3 (48-col slice)
    const int row0 = blockIdx.x * 128;

    // ldmatrix per-thread addressing components
    const int ar  = lane & 15;
    const int ak8 = (lane & 16) >> 1;              // +8 k if lane>=16
    const int bn  = (lane & 7) + ((lane & 16) >> 1);
    const int bk8 = ((lane >> 3) & 1) << 3;

    float acc[4][6][4];
#pragma unroll
    for (int i = 0; i < 4; i++)
#pragma unroll
        for (int j = 0; j < 6; j++)
#pragma unroll
            for (int q = 0; q < 4; q++) acc[i][j][q] = 0.f;

    float4 ra[4], rb[6];
    // initial global loads (kt = 0)
#pragma unroll
    for (int l = 0; l < 4; l++) {
        int idx = tid + l * 256, r = idx >> 3, k4 = (idx & 7) << 2;
        ra[l] = *(const float4*)(x + (size_t)(row0 + r) * NC + k4);
    }
#pragma unroll
    for (int l = 0; l < 6; l++) {
        int idx = tid + l * 256, r = idx >> 3, k4 = (idx & 7) << 2;
        const float* W = (r < 64) ? Wq : (r < 128) ? Wk : Wv;
        rb[l] = *(const float4*)(W + (size_t)(r & 63) * NC + k4);
    }

    for (int kt = 0; kt < NC; kt += 32) {
        __syncthreads();   // previous mma done before smem overwrite
        // convert + store tile
#pragma unroll
        for (int l = 0; l < 4; l++) {
            int idx = tid + l * 256, r = idx >> 3, k4 = (idx & 7) << 2;
            uint32_t h0, l0, h1, l1;
            split2(ra[l].x, ra[l].y, h0, l0);
            split2(ra[l].z, ra[l].w, h1, l1);
            int o = r * 20 + (k4 >> 1);
            s32[(P_AH >> 2) + o] = h0; s32[(P_AH >> 2) + o + 1] = h1;
            s32[(P_AL >> 2) + o] = l0; s32[(P_AL >> 2) + o + 1] = l1;
        }
#pragma unroll
        for (int l = 0; l < 6; l++) {
            int idx = tid + l * 256, r = idx >> 3, k4 = (idx & 7) << 2;
            uint32_t h0, l0, h1, l1;
            split2(rb[l].x, rb[l].y, h0, l0);
            split2(rb[l].z, rb[l].w, h1, l1);
            int o = r * 20 + (k4 >> 1);
            s32[(P_BH >> 2) + o] = h0; s32[(P_BH >> 2) + o + 1] = h1;
            s32[(P_BL >> 2) + o] = l0; s32[(P_BL >> 2) + o + 1] = l1;
        }
        __syncthreads();

        // prefetch next tile (latency overlaps mma below)
        if (kt + 32 < NC) {
            int kn = kt + 32;
#pragma unroll
            for (int l = 0; l < 4; l++) {
                int idx = tid + l * 256, r = idx >> 3, k4 = (idx & 7) << 2;
                ra[l] = *(const float4*)(x + (size_t)(row0 + r) * NC + kn + k4);
            }
#pragma unroll
            for (int l = 0; l < 6; l++) {
                int idx = tid + l * 256, r = idx >> 3, k4 = (idx & 7) << 2;
                const float* W = (r < 64) ? Wq : (r < 128) ? Wk : Wv;
                rb[l] = *(const float4*)(W + (size_t)(r & 63) * NC + kn + k4);
            }
        }

        // MMA: 2 k16 steps
#pragma unroll
        for (int ks = 0; ks < 2; ks++) {
            const int kb = ks * 16;
            uint32_t bh[12], bl[12];
#pragma unroll
            for (int jp = 0; jp < 3; jp++) {
                int n0 = wn * 48 + jp * 16;
                uint32_t off = (uint32_t)(n0 + bn) * 80 + (uint32_t)(kb + bk8) * 2;
                ldsm4(sb + P_BH + off, bh[4*jp], bh[4*jp+1], bh[4*jp+2], bh[4*jp+3]);
                ldsm4(sb + P_BL + off, bl[4*jp], bl[4*jp+1], bl[4*jp+2], bl[4*jp+3]);
            }
#pragma unroll
            for (int mf = 0; mf < 4; mf++) {
                int r0l = wm * 64 + mf * 16;
                uint32_t aoff = (uint32_t)(r0l + ar) * 80 + (uint32_t)(kb + ak8) * 2;
                uint32_t ah[4], al[4];
                ldsm4(sb + P_AH + aoff, ah[0], ah[1], ah[2], ah[3]);
                ldsm4(sb + P_AL + aoff, al[0], al[1], al[2], al[3]);
#pragma unroll
                for (int nf = 0; nf < 6; nf++) {
                    mma16816(acc[mf][nf], ah, bh[2*nf], bh[2*nf+1]);
                    mma16816(acc[mf][nf], ah, bl[2*nf], bl[2*nf+1]);
                    mma16816(acc[mf][nf], al, bh[2*nf], bh[2*nf+1]);
                }
            }
        }
    }

    // ---- epilogue: split fp32 acc -> bf16 hi/lo scratch ----
    const int bq = row0 >> 11;   // batch index (2048 rows per batch)
#pragma unroll
    for (int mf = 0; mf < 4; mf++) {
        int rl = wm * 64 + mf * 16 + (lane >> 2);
        size_t r0 = (size_t)row0 + rl;
#pragma unroll
        for (int nf = 0; nf < 6; nf++) {
            int c = wn * 48 + nf * 8 + ((lane & 3) << 1);
            float v00 = acc[mf][nf][0], v01 = acc[mf][nf][1];
            float v10 = acc[mf][nf][2], v11 = acc[mf][nf][3];
            int mat = c >> 6, lc = c & 63;
            if (mat == 0) { v00 *= QSCALE; v01 *= QSCALE; v10 *= QSCALE; v11 *= QSCALE; }
            uint32_t h0, l0, h1, l1;
            split2(v00, v01, h0, l0);
            split2(v10, v11, h1, l1);
            if (mat == 0) {
                *(uint32_t*)&g_qh[r0 * NH + lc]       = h0;
                *(uint32_t*)&g_qh[(r0 + 8) * NH + lc] = h1;
                *(uint32_t*)&g_ql[r0 * NH + lc]       = l0;
                *(uint32_t*)&g_ql[(r0 + 8) * NH + lc] = l1;
            } else if (mat == 1) {
                *(uint32_t*)&g_kh[r0 * NH + lc]       = h0;
                *(uint32_t*)&g_kh[(r0 + 8) * NH + lc] = h1;
                *(uint32_t*)&g_kl[r0 * NH + lc]       = l0;
                *(uint32_t*)&g_kl[(r0 + 8) * NH + lc] = l1;
            } else {
                // v transposed: g_vt[b][h][t]
                __nv_bfloat162 H0 = *(__nv_bfloat162*)&h0;
                __nv_bfloat162 H1 = *(__nv_bfloat162*)&h1;
                __nv_bfloat162 L0 = *(__nv_bfloat162*)&l0;
                __nv_bfloat162 L1 = *(__nv_bfloat162*)&l1;
                size_t t0 = r0 & 2047;
                size_t base = ((size_t)bq * NH + lc) * NT + t0;
                g_vth[base]          = H0.x;  g_vth[base + 8]      = H1.x;
                g_vth[base + NT]     = H0.y;  g_vth[base + NT + 8] = H1.y;
                g_vtl[base]          = L0.x;  g_vtl[base + 8]      = L1.x;
                g_vtl[base + NT]     = L0.y;  g_vtl[base + NT + 8] = L1.y;
            }
        }
    }
}

// ===========================================================================
// Kernel 2: flash attention, split-bf16 HMMA, register-resident softmax.
// BQ=64, 4 warps x 16 rows; KV tiles of 64 double-buffered via cp.async.
// Mirrored causal schedule: block bx does q-tiles {bx, 31-bx} (33 iters).
// ===========================================================================
// smem: rows padded to 72 bf16 = 144 B
#define A_QH   0
#define A_QL   9216
#define A_KV   18432
#define A_TILE 9216
#define A_SMEM (A_KV + 8 * A_TILE)   // 92160

__device__ __forceinline__ void issue_q(uint32_t sb, int b, int q0, int tid) {
#pragma unroll
    for (int l = 0; l < 8; l++) {
        int idx = tid + l * 128;
        int part = idx >> 9, rem = idx & 511, r = rem >> 3, s = rem & 7;
        const __nv_bfloat16* src =
            (part ? g_ql : g_qh) + ((size_t)(b * NT + q0 + r) * NH + s * 8);
        uint32_t dst = sb + (part ? A_QL : A_QH) + (uint32_t)r * 144 + s * 16;
        CP_ASYNC16(dst, src);
    }
}

__device__ __forceinline__ void issue_kv(uint32_t sb, int b, int c0, int buf, int tid) {
#pragma unroll
    for (int l = 0; l < 16; l++) {
        int idx = tid + l * 128;
        int w = idx >> 9, rem = idx & 511, r = rem >> 3, s = rem & 7;
        const __nv_bfloat16* src;
        if (w == 0)      src = g_kh  + ((size_t)(b * NT + c0 + r) * NH + s * 8);
        else if (w == 1) src = g_kl  + ((size_t)(b * NT + c0 + r) * NH + s * 8);
        else if (w == 2) src = g_vth + ((size_t)(b * NH + r) * NT + c0 + s * 8);
        else             src = g_vtl + ((size_t)(b * NH + r) * NT + c0 + s * 8);
        uint32_t dst = sb + A_KV + (uint32_t)(buf * 4 + w) * A_TILE
                       + (uint32_t)r * 144 + s * 16;
        CP_ASYNC16(dst, src);
    }
}

__global__ __launch_bounds__(128) void attn_mma_kernel(float* __restrict__ out)
{
    extern __shared__ char smraw[];
    uint32_t sb = smem_u32(smraw);
    const int tid  = threadIdx.x;
    const int lane = tid & 31;
    const int warp = tid >> 5;
    const int b    = blockIdx.y;
    const int w16  = warp * 16;

    const int ar  = lane & 15;
    const int ak8 = (lane & 16) >> 1;
    const int bn  = (lane & 7) + ((lane & 16) >> 1);
    const int bk8 = ((lane >> 3) & 1) << 3;
    const uint32_t boff = (uint32_t)bn * 144 + (uint32_t)bk8 * 2;

    for (int pass = 0; pass < 2; pass++) {
        const int qi = pass ? (31 - blockIdx.x) : blockIdx.x;
        const int q0 = qi * 64;

        issue_q(sb, b, q0, tid);  CP_COMMIT();
        issue_kv(sb, b, 0, 0, tid); CP_COMMIT();
        CP_WAIT1();               // Q group complete
        __syncthreads();

        // Q fragments, resident for the whole pass
        uint32_t qfh[16], qfl[16];
#pragma unroll
        for (int ks = 0; ks < 4; ks++) {
            uint32_t a = sb + A_QH + (uint32_t)(w16 + ar) * 144
                         + (uint32_t)(ks * 16 + ak8) * 2;
            ldsm4(a,        qfh[ks*4], qfh[ks*4+1], qfh[ks*4+2], qfh[ks*4+3]);
            ldsm4(a + 9216, qfl[ks*4], qfl[ks*4+1], qfl[ks*4+2], qfl[ks*4+3]);
        }

        float m0 = -1e30f, m1 = -1e30f, l0s = 0.f, l1s = 0.f;
        float o[8][4];
#pragma unroll
        for (int i = 0; i < 8; i++)
#pragma unroll
            for (int j = 0; j < 4; j++) o[i][j] = 0.f;

        for (int kj = 0; kj <= qi; kj++) {
            if (kj < qi) {
                issue_kv(sb, b, (kj + 1) * 64, (kj + 1) & 1, tid);
                CP_COMMIT();
                CP_WAIT1();
            } else {
                CP_WAIT0();
            }
            __syncthreads();

            const uint32_t khb = sb + A_KV + (uint32_t)((kj & 1) * 4 + 0) * A_TILE;
            const uint32_t klb = khb + A_TILE;
            const uint32_t vhb = khb + 2 * A_TILE;
            const uint32_t vlb = khb + 3 * A_TILE;

            // ---- S = Qs . K^T (3-term split) ----
            float s[8][4];
#pragma unroll
            for (int i = 0; i < 8; i++)
#pragma unroll
                for (int j = 0; j < 4; j++) s[i][j] = 0.f;

#pragma unroll
            for (int ks = 0; ks < 4; ks++) {
                const uint32_t* qh = &qfh[ks * 4];
                const uint32_t* ql = &qfl[ks * 4];
#pragma unroll
                for (int p = 0; p < 4; p++) {
                    uint32_t off = (uint32_t)(p * 16) * 144 + (uint32_t)(ks * 16) * 2 + boff;
                    uint32_t h0, h1, h2, h3, e0, e1, e2, e3;
                    ldsm4(khb + off, h0, h1, h2, h3);
                    ldsm4(klb + off, e0, e1, e2, e3);
                    mma16816(s[2*p],   qh, h0, h1);
                    mma16816(s[2*p],   qh, e0, e1);
                    mma16816(s[2*p],   ql, h0, h1);
                    mma16816(s[2*p+1], qh, h2, h3);
                    mma16816(s[2*p+1], qh, e2, e3);
                    mma16816(s[2*p+1], ql, h2, h3);
                }
            }

            // ---- causal mask (diagonal tile only) ----
            if (kj == qi) {
                int rl0 = w16 + (lane >> 2);
#pragma unroll
                for (int nf = 0; nf < 8; nf++) {
                    int c = nf * 8 + ((lane & 3) << 1);
                    if (c     > rl0)     s[nf][0] = -1e30f;
                    if (c + 1 > rl0)     s[nf][1] = -1e30f;
                    if (c     > rl0 + 8) s[nf][2] = -1e30f;
                    if (c + 1 > rl0 + 8) s[nf][3] = -1e30f;
                }
            }

            // ---- online softmax (base 2; scale pre-folded into Q) ----
            float tm0 = -1e30f, tm1 = -1e30f;
#pragma unroll
            for (int nf = 0; nf < 8; nf++) {
                tm0 = fmaxf(tm0, fmaxf(s[nf][0], s[nf][1]));
                tm1 = fmaxf(tm1, fmaxf(s[nf][2], s[nf][3]));
            }
            tm0 = fmaxf(tm0, __shfl_xor_sync(0xffffffffu, tm0, 1));
            tm0 = fmaxf(tm0, __shfl_xor_sync(0xffffffffu, tm0, 2));
            tm1 = fmaxf(tm1, __shfl_xor_sync(0xffffffffu, tm1, 1));
            tm1 = fmaxf(tm1, __shfl_xor_sync(0xffffffffu, tm1, 2));
            float mn0 = fmaxf(m0, tm0), mn1 = fmaxf(m1, tm1);
            float c0 = exp2f(m0 - mn0), c1 = exp2f(m1 - mn1);
            m0 = mn0; m1 = mn1;
#pragma unroll
            for (int nf = 0; nf < 8; nf++) {
                o[nf][0] *= c0; o[nf][1] *= c0;
                o[nf][2] *= c1; o[nf][3] *= c1;
            }
            float ps0 = 0.f, ps1 = 0.f;
#pragma unroll
            for (int nf = 0; nf < 8; nf++) {
                s[nf][0] = exp2f(s[nf][0] - mn0);
                s[nf][1] = exp2f(s[nf][1] - mn0);
                s[nf][2] = exp2f(s[nf][2] - mn1);
                s[nf][3] = exp2f(s[nf][3] - mn1);
                ps0 += s[nf][0] + s[nf][1];
                ps1 += s[nf][2] + s[nf][3];
            }
            ps0 += __shfl_xor_sync(0xffffffffu, ps0, 1);
            ps0 += __shfl_xor_sync(0xffffffffu, ps0, 2);
            ps1 += __shfl_xor_sync(0xffffffffu, ps1, 1);
            ps1 += __shfl_xor_sync(0xffffffffu, ps1, 2);
            l0s = l0s * c0 + ps0;
            l1s = l1s * c1 + ps1;

            // ---- O += P . V (P repacked in registers as A-fragments) ----
#pragma unroll
            for (int ks = 0; ks < 4; ks++) {
                uint32_t ph[4], pl[4];
                split2(s[2*ks][0],   s[2*ks][1],   ph[0], pl[0]);
                split2(s[2*ks][2],   s[2*ks][3],   ph[1], pl[1]);
                split2(s[2*ks+1][0], s[2*ks+1][1], ph[2], pl[2]);
                split2(s[2*ks+1][2], s[2*ks+1][3], ph[3], pl[3]);
#pragma unroll
                for (int p = 0; p < 4; p++) {
                    uint32_t off = (uint32_t)(p * 16) * 144 + (uint32_t)(ks * 16) * 2 + boff;
                    uint32_t h0, h1, h2, h3, e0, e1, e2, e3;
                    ldsm4(vhb + off, h0, h1, h2, h3);
                    ldsm4(vlb + off, e0, e1, e2, e3);
                    mma16816(o[2*p],   ph, h0, h1);
                    mma16816(o[2*p],   ph, e0, e1);
                    mma16816(o[2*p],   pl, h0, h1);
                    mma16816(o[2*p+1], ph, h2, h3);
                    mma16816(o[2*p+1], ph, e2, e3);
                    mma16816(o[2*p+1], pl, h2, h3);
                }
            }
            __syncthreads();   // all warps done before buffer reuse
        }

        // ---- finalize & store ----
        float inv0 = 1.f / l0s, inv1 = 1.f / l1s;
        int t0 = q0 + w16 + (lane >> 2);
        size_t rowb = ((size_t)b * NT + t0) * NH;
#pragma unroll
        for (int nf = 0; nf < 8; nf++) {
            int h = nf * 8 + ((lane & 3) << 1);
            float2 f0 = make_float2(o[nf][0] * inv0, o[nf][1] * inv0);
            float2 f1 = make_float2(o[nf][2] * inv1, o[nf][3] * inv1);
            *(float2*)&out[rowb + h]          = f0;
            *(float2*)&out[rowb + 8 * NH + h] = f1;
        }
        __syncthreads();
    }
}

// ===========================================================================
extern "C" void kernel_launch(void* const* d_in, const int* in_sizes, int n_in,
                              void* d_out, int out_size)
{
    (void)in_sizes; (void)n_in; (void)out_size;
    const float* x  = (const float*)d_in[0];
    const float* Wk = (const float*)d_in[1];
    const float* Wq = (const float*)d_in[2];
    const float* Wv = (const float*)d_in[3];
    float* out = (float*)d_out;

    cudaFuncSetAttribute(qkv_mma_kernel,
                         cudaFuncAttributeMaxDynamicSharedMemorySize, P_SMEM);
    cudaFuncSetAttribute(attn_mma_kernel,
                         cudaFuncAttributeMaxDynamicSharedMemorySize, A_SMEM);

    qkv_mma_kernel<<<NM / 128, 256, P_SMEM>>>(x, Wq, Wk, Wv);
    attn_mma_kernel<<<dim3(16, NB), 128, A_SMEM>>>(out);
}

// round 6
// speedup vs baseline: 3.5710x; 1.0022x over previous
#include <cuda_runtime.h>
#include <cuda_bf16.h>
#include <cstdint>

// Problem constants
#define NB 8
#define NT 2048
#define NC 1024
#define NH 64
#define NM (NB * NT)   // 16384 rows

#define QSCALE (1.4426950408889634f / 32.0f)   // log2(e)/sqrt(C)

// Split-bf16 scratch: q (pre-scaled), k as [b][t][h]; v transposed [b][h][t].
__device__ __nv_bfloat16 g_qh[NM * NH];
__device__ __nv_bfloat16 g_ql[NM * NH];
__device__ __nv_bfloat16 g_kh[NM * NH];
__device__ __nv_bfloat16 g_kl[NM * NH];
__device__ __nv_bfloat16 g_vth[NB * NH * NT];
__device__ __nv_bfloat16 g_vtl[NB * NH * NT];

// ===========================================================================
// Helpers (baseline PTX only: ldmatrix / mma.sync / cp.async — NO tcgen05)
// ===========================================================================
__device__ __forceinline__ uint32_t smem_u32(const void* p) {
    uint32_t a;
    asm("{ .reg .u64 t; cvta.to.shared.u64 t, %1; cvt.u32.u64 %0, t; }"
        : "=r"(a) : "l"(p));
    return a;
}

__device__ __forceinline__ void ldsm4(uint32_t addr, uint32_t& r0, uint32_t& r1,
                                      uint32_t& r2, uint32_t& r3) {
    asm volatile("ldmatrix.sync.aligned.m8n8.x4.shared.b16 {%0,%1,%2,%3}, [%4];\n"
                 : "=r"(r0), "=r"(r1), "=r"(r2), "=r"(r3) : "r"(addr));
}

// D(+=) A(16x16 bf16) * B(16x8 bf16), fp32 accum, in-place C
__device__ __forceinline__ void mma16816(float* d, const uint32_t* a,
                                         uint32_t b0, uint32_t b1) {
    asm volatile(
        "mma.sync.aligned.m16n8k16.row.col.f32.bf16.bf16.f32 "
        "{%0,%1,%2,%3}, {%4,%5,%6,%7}, {%8,%9}, {%0,%1,%2,%3};\n"
        : "+f"(d[0]), "+f"(d[1]), "+f"(d[2]), "+f"(d[3])
        : "r"(a[0]), "r"(a[1]), "r"(a[2]), "r"(a[3]), "r"(b0), "r"(b1));
}

#define CP_ASYNC16(dst, src) \
    asm volatile("cp.async.cg.shared.global [%0], [%1], 16;\n" :: "r"(dst), "l"(src))
#define CP_COMMIT() asm volatile("cp.async.commit_group;\n" ::: "memory")
#define CP_WAIT1()  asm volatile("cp.async.wait_group 1;\n" ::: "memory")
#define CP_WAIT0()  asm volatile("cp.async.wait_group 0;\n" ::: "memory")

// Split two fp32 into packed bf16x2 (hi) and packed bf16x2 (residual lo).
__device__ __forceinline__ void split2(float v0, float v1, uint32_t& hi, uint32_t& lo) {
    __nv_bfloat162 h = __floats2bfloat162_rn(v0, v1);
    float r0 = v0 - __bfloat162float(h.x);
    float r1 = v1 - __bfloat162float(h.y);
    __nv_bfloat162 l = __floats2bfloat162_rn(r0, r1);
    hi = *reinterpret_cast<uint32_t*>(&h);
    lo = *reinterpret_cast<uint32_t*>(&l);
}

// ===========================================================================
// Kernel 1: fused QKV projection, split-bf16 HMMA.
// out[m, c] for c in [0,192): 0-63 q (pre-scaled), 64-127 k, 128-191 v.
// Block: 128 rows x 192 cols, 8 warps (2x4), BK=32.
// ===========================================================================
// smem byte offsets (bf16 rows padded to 40 elems = 80 B for conflict-free ldsm)
#define P_AH 0
#define P_AL 10240
#define P_BH 20480
#define P_BL 35840
#define P_SMEM 51200

__global__ __launch_bounds__(256) void qkv_mma_kernel(
    const float* __restrict__ x,
    const float* __restrict__ Wq,
    const float* __restrict__ Wk,
    const float* __restrict__ Wv)
{
    extern __shared__ char smraw[];
    uint32_t sb = smem_u32(smraw);
    uint32_t* s32 = (uint32_t*)smraw;

    const int tid  = threadIdx.x;
    const int lane = tid & 31;
    const int wid  = tid >> 5;
    const int wm   = wid >> 2;      // 0..1 (row half)
    const int wn   = wid & 3;       // 0..3 (48-col slice)
    const int row0 = blockIdx.x * 128;

    // ldmatrix per-thread addressing components
    const int ar  = lane & 15;
    const int ak8 = (lane & 16) >> 1;              // +8 k if lane>=16
    const int bn  = (lane & 7) + ((lane & 16) >> 1);
    const int bk8 = ((lane >> 3) & 1) << 3;

    float acc[4][6][4];
#pragma unroll
    for (int i = 0; i < 4; i++)
#pragma unroll
        for (int j = 0; j < 6; j++)
#pragma unroll
            for (int q = 0; q < 4; q++) acc[i][j][q] = 0.f;

    float4 ra[4], rb[6];
    // initial global loads (kt = 0)
#pragma unroll
    for (int l = 0; l < 4; l++) {
        int idx = tid + l * 256, r = idx >> 3, k4 = (idx & 7) << 2;
        ra[l] = *(const float4*)(x + (size_t)(row0 + r) * NC + k4);
    }
#pragma unroll
    for (int l = 0; l < 6; l++) {
        int idx = tid + l * 256, r = idx >> 3, k4 = (idx & 7) << 2;
        const float* W = (r < 64) ? Wq : (r < 128) ? Wk : Wv;
        rb[l] = *(const float4*)(W + (size_t)(r & 63) * NC + k4);
    }

    for (int kt = 0; kt < NC; kt += 32) {
        __syncthreads();   // previous mma done before smem overwrite
        // convert + store tile
#pragma unroll
        for (int l = 0; l < 4; l++) {
            int idx = tid + l * 256, r = idx >> 3, k4 = (idx & 7) << 2;
            uint32_t h0, l0, h1, l1;
            split2(ra[l].x, ra[l].y, h0, l0);
            split2(ra[l].z, ra[l].w, h1, l1);
            int o = r * 20 + (k4 >> 1);
            s32[(P_AH >> 2) + o] = h0; s32[(P_AH >> 2) + o + 1] = h1;
            s32[(P_AL >> 2) + o] = l0; s32[(P_AL >> 2) + o + 1] = l1;
        }
#pragma unroll
        for (int l = 0; l < 6; l++) {
            int idx = tid + l * 256, r = idx >> 3, k4 = (idx & 7) << 2;
            uint32_t h0, l0, h1, l1;
            split2(rb[l].x, rb[l].y, h0, l0);
            split2(rb[l].z, rb[l].w, h1, l1);
            int o = r * 20 + (k4 >> 1);
            s32[(P_BH >> 2) + o] = h0; s32[(P_BH >> 2) + o + 1] = h1;
            s32[(P_BL >> 2) + o] = l0; s32[(P_BL >> 2) + o + 1] = l1;
        }
        __syncthreads();

        // prefetch next tile (latency overlaps mma below)
        if (kt + 32 < NC) {
            int kn = kt + 32;
#pragma unroll
            for (int l = 0; l < 4; l++) {
                int idx = tid + l * 256, r = idx >> 3, k4 = (idx & 7) << 2;
                ra[l] = *(const float4*)(x + (size_t)(row0 + r) * NC + kn + k4);
            }
#pragma unroll
            for (int l = 0; l < 6; l++) {
                int idx = tid + l * 256, r = idx >> 3, k4 = (idx & 7) << 2;
                const float* W = (r < 64) ? Wq : (r < 128) ? Wk : Wv;
                rb[l] = *(const float4*)(W + (size_t)(r & 63) * NC + kn + k4);
            }
        }

        // MMA: 2 k16 steps
#pragma unroll
        for (int ks = 0; ks < 2; ks++) {
            const int kb = ks * 16;
            uint32_t bh[12], bl[12];
#pragma unroll
            for (int jp = 0; jp < 3; jp++) {
                int n0 = wn * 48 + jp * 16;
                uint32_t off = (uint32_t)(n0 + bn) * 80 + (uint32_t)(kb + bk8) * 2;
                ldsm4(sb + P_BH + off, bh[4*jp], bh[4*jp+1], bh[4*jp+2], bh[4*jp+3]);
                ldsm4(sb + P_BL + off, bl[4*jp], bl[4*jp+1], bl[4*jp+2], bl[4*jp+3]);
            }
#pragma unroll
            for (int mf = 0; mf < 4; mf++) {
                int r0l = wm * 64 + mf * 16;
                uint32_t aoff = (uint32_t)(r0l + ar) * 80 + (uint32_t)(kb + ak8) * 2;
                uint32_t ah[4], al[4];
                ldsm4(sb + P_AH + aoff, ah[0], ah[1], ah[2], ah[3]);
                ldsm4(sb + P_AL + aoff, al[0], al[1], al[2], al[3]);
#pragma unroll
                for (int nf = 0; nf < 6; nf++) {
                    mma16816(acc[mf][nf], ah, bh[2*nf], bh[2*nf+1]);
                    mma16816(acc[mf][nf], ah, bl[2*nf], bl[2*nf+1]);
                    mma16816(acc[mf][nf], al, bh[2*nf], bh[2*nf+1]);
                }
            }
        }
    }

    // ---- epilogue: split fp32 acc -> bf16 hi/lo scratch ----
    const int bq = row0 >> 11;   // batch index (2048 rows per batch)
#pragma unroll
    for (int mf = 0; mf < 4; mf++) {
        int rl = wm * 64 + mf * 16 + (lane >> 2);
        size_t r0 = (size_t)row0 + rl;
#pragma unroll
        for (int nf = 0; nf < 6; nf++) {
            int c = wn * 48 + nf * 8 + ((lane & 3) << 1);
            float v00 = acc[mf][nf][0], v01 = acc[mf][nf][1];
            float v10 = acc[mf][nf][2], v11 = acc[mf][nf][3];
            int mat = c >> 6, lc = c & 63;
            if (mat == 0) { v00 *= QSCALE; v01 *= QSCALE; v10 *= QSCALE; v11 *= QSCALE; }
            uint32_t h0, l0, h1, l1;
            split2(v00, v01, h0, l0);
            split2(v10, v11, h1, l1);
            if (mat == 0) {
                *(uint32_t*)&g_qh[r0 * NH + lc]       = h0;
                *(uint32_t*)&g_qh[(r0 + 8) * NH + lc] = h1;
                *(uint32_t*)&g_ql[r0 * NH + lc]       = l0;
                *(uint32_t*)&g_ql[(r0 + 8) * NH + lc] = l1;
            } else if (mat == 1) {
                *(uint32_t*)&g_kh[r0 * NH + lc]       = h0;
                *(uint32_t*)&g_kh[(r0 + 8) * NH + lc] = h1;
                *(uint32_t*)&g_kl[r0 * NH + lc]       = l0;
                *(uint32_t*)&g_kl[(r0 + 8) * NH + lc] = l1;
            } else {
                // v transposed: g_vt[b][h][t]
                __nv_bfloat162 H0 = *(__nv_bfloat162*)&h0;
                __nv_bfloat162 H1 = *(__nv_bfloat162*)&h1;
                __nv_bfloat162 L0 = *(__nv_bfloat162*)&l0;
                __nv_bfloat162 L1 = *(__nv_bfloat162*)&l1;
                size_t t0 = r0 & 2047;
                size_t base = ((size_t)bq * NH + lc) * NT + t0;
                g_vth[base]          = H0.x;  g_vth[base + 8]      = H1.x;
                g_vth[base + NT]     = H0.y;  g_vth[base + NT + 8] = H1.y;
                g_vtl[base]          = L0.x;  g_vtl[base + 8]      = L1.x;
                g_vtl[base + NT]     = L0.y;  g_vtl[base + NT + 8] = L1.y;
            }
        }
    }
}

// ===========================================================================
// Kernel 2: flash attention, split-bf16 HMMA, register-resident softmax.
// BQ=64, 4 warps x 16 rows; KV tiles of 64 double-buffered via cp.async.
// Mirrored causal schedule: block bx does q-tiles {bx, 31-bx} (33 iters).
// ===========================================================================
// smem: rows padded to 72 bf16 = 144 B
#define A_QH   0
#define A_QL   9216
#define A_KV   18432
#define A_TILE 9216
#define A_SMEM (A_KV + 8 * A_TILE)   // 92160

__device__ __forceinline__ void issue_q(uint32_t sb, int b, int q0, int tid) {
#pragma unroll
    for (int l = 0; l < 8; l++) {
        int idx = tid + l * 128;
        int part = idx >> 9, rem = idx & 511, r = rem >> 3, s = rem & 7;
        const __nv_bfloat16* src =
            (part ? g_ql : g_qh) + ((size_t)(b * NT + q0 + r) * NH + s * 8);
        uint32_t dst = sb + (part ? A_QL : A_QH) + (uint32_t)r * 144 + s * 16;
        CP_ASYNC16(dst, src);
    }
}

__device__ __forceinline__ void issue_kv(uint32_t sb, int b, int c0, int buf, int tid) {
#pragma unroll
    for (int l = 0; l < 16; l++) {
        int idx = tid + l * 128;
        int w = idx >> 9, rem = idx & 511, r = rem >> 3, s = rem & 7;
        const __nv_bfloat16* src;
        if (w == 0)      src = g_kh  + ((size_t)(b * NT + c0 + r) * NH + s * 8);
        else if (w == 1) src = g_kl  + ((size_t)(b * NT + c0 + r) * NH + s * 8);
        else if (w == 2) src = g_vth + ((size_t)(b * NH + r) * NT + c0 + s * 8);
        else             src = g_vtl + ((size_t)(b * NH + r) * NT + c0 + s * 8);
        uint32_t dst = sb + A_KV + (uint32_t)(buf * 4 + w) * A_TILE
                       + (uint32_t)r * 144 + s * 16;
        CP_ASYNC16(dst, src);
    }
}

__global__ __launch_bounds__(128) void attn_mma_kernel(float* __restrict__ out)
{
    extern __shared__ char smraw[];
    uint32_t sb = smem_u32(smraw);
    const int tid  = threadIdx.x;
    const int lane = tid & 31;
    const int warp = tid >> 5;
    const int b    = blockIdx.y;
    const int w16  = warp * 16;

    const int ar  = lane & 15;
    const int ak8 = (lane & 16) >> 1;
    const int bn  = (lane & 7) + ((lane & 16) >> 1);
    const int bk8 = ((lane >> 3) & 1) << 3;
    const uint32_t boff = (uint32_t)bn * 144 + (uint32_t)bk8 * 2;

    for (int pass = 0; pass < 2; pass++) {
        const int qi = pass ? (31 - blockIdx.x) : blockIdx.x;
        const int q0 = qi * 64;

        issue_q(sb, b, q0, tid);  CP_COMMIT();
        issue_kv(sb, b, 0, 0, tid); CP_COMMIT();
        CP_WAIT1();               // Q group complete
        __syncthreads();

        // Q fragments, resident for the whole pass
        uint32_t qfh[16], qfl[16];
#pragma unroll
        for (int ks = 0; ks < 4; ks++) {
            uint32_t a = sb + A_QH + (uint32_t)(w16 + ar) * 144
                         + (uint32_t)(ks * 16 + ak8) * 2;
            ldsm4(a,        qfh[ks*4], qfh[ks*4+1], qfh[ks*4+2], qfh[ks*4+3]);
            ldsm4(a + 9216, qfl[ks*4], qfl[ks*4+1], qfl[ks*4+2], qfl[ks*4+3]);
        }

        float m0 = -1e30f, m1 = -1e30f, l0s = 0.f, l1s = 0.f;
        float o[8][4];
#pragma unroll
        for (int i = 0; i < 8; i++)
#pragma unroll
            for (int j = 0; j < 4; j++) o[i][j] = 0.f;

        for (int kj = 0; kj <= qi; kj++) {
            if (kj < qi) {
                issue_kv(sb, b, (kj + 1) * 64, (kj + 1) & 1, tid);
                CP_COMMIT();
                CP_WAIT1();
            } else {
                CP_WAIT0();
            }
            __syncthreads();

            const uint32_t khb = sb + A_KV + (uint32_t)((kj & 1) * 4 + 0) * A_TILE;
            const uint32_t klb = khb + A_TILE;
            const uint32_t vhb = khb + 2 * A_TILE;
            const uint32_t vlb = khb + 3 * A_TILE;

            // ---- S = Qs . K^T (3-term split) ----
            float s[8][4];
#pragma unroll
            for (int i = 0; i < 8; i++)
#pragma unroll
                for (int j = 0; j < 4; j++) s[i][j] = 0.f;

#pragma unroll
            for (int ks = 0; ks < 4; ks++) {
                const uint32_t* qh = &qfh[ks * 4];
                const uint32_t* ql = &qfl[ks * 4];
#pragma unroll
                for (int p = 0; p < 4; p++) {
                    uint32_t off = (uint32_t)(p * 16) * 144 + (uint32_t)(ks * 16) * 2 + boff;
                    uint32_t h0, h1, h2, h3, e0, e1, e2, e3;
                    ldsm4(khb + off, h0, h1, h2, h3);
                    ldsm4(klb + off, e0, e1, e2, e3);
                    mma16816(s[2*p],   qh, h0, h1);
                    mma16816(s[2*p],   qh, e0, e1);
                    mma16816(s[2*p],   ql, h0, h1);
                    mma16816(s[2*p+1], qh, h2, h3);
                    mma16816(s[2*p+1], qh, e2, e3);
                    mma16816(s[2*p+1], ql, h2, h3);
                }
            }

            // ---- causal mask (diagonal tile only) ----
            if (kj == qi) {
                int rl0 = w16 + (lane >> 2);
#pragma unroll
                for (int nf = 0; nf < 8; nf++) {
                    int c = nf * 8 + ((lane & 3) << 1);
                    if (c     > rl0)     s[nf][0] = -1e30f;
                    if (c + 1 > rl0)     s[nf][1] = -1e30f;
                    if (c     > rl0 + 8) s[nf][2] = -1e30f;
                    if (c + 1 > rl0 + 8) s[nf][3] = -1e30f;
                }
            }

            // ---- online softmax (base 2; scale pre-folded into Q) ----
            float tm0 = -1e30f, tm1 = -1e30f;
#pragma unroll
            for (int nf = 0; nf < 8; nf++) {
                tm0 = fmaxf(tm0, fmaxf(s[nf][0], s[nf][1]));
                tm1 = fmaxf(tm1, fmaxf(s[nf][2], s[nf][3]));
            }
            tm0 = fmaxf(tm0, __shfl_xor_sync(0xffffffffu, tm0, 1));
            tm0 = fmaxf(tm0, __shfl_xor_sync(0xffffffffu, tm0, 2));
            tm1 = fmaxf(tm1, __shfl_xor_sync(0xffffffffu, tm1, 1));
            tm1 = fmaxf(tm1, __shfl_xor_sync(0xffffffffu, tm1, 2));
            float mn0 = fmaxf(m0, tm0), mn1 = fmaxf(m1, tm1);
            float c0 = exp2f(m0 - mn0), c1 = exp2f(m1 - mn1);
            m0 = mn0; m1 = mn1;
#pragma unroll
            for (int nf = 0; nf < 8; nf++) {
                o[nf][0] *= c0; o[nf][1] *= c0;
                o[nf][2] *= c1; o[nf][3] *= c1;
            }
            float ps0 = 0.f, ps1 = 0.f;
#pragma unroll
            for (int nf = 0; nf < 8; nf++) {
                s[nf][0] = exp2f(s[nf][0] - mn0);
                s[nf][1] = exp2f(s[nf][1] - mn0);
                s[nf][2] = exp2f(s[nf][2] - mn1);
                s[nf][3] = exp2f(s[nf][3] - mn1);
                ps0 += s[nf][0] + s[nf][1];
                ps1 += s[nf][2] + s[nf][3];
            }
            ps0 += __shfl_xor_sync(0xffffffffu, ps0, 1);
            ps0 += __shfl_xor_sync(0xffffffffu, ps0, 2);
            ps1 += __shfl_xor_sync(0xffffffffu, ps1, 1);
            ps1 += __shfl_xor_sync(0xffffffffu, ps1, 2);
            l0s = l0s * c0 + ps0;
            l1s = l1s * c1 + ps1;

            // ---- O += P . V (P repacked in registers as A-fragments) ----
#pragma unroll
            for (int ks = 0; ks < 4; ks++) {
                uint32_t ph[4], pl[4];
                split2(s[2*ks][0],   s[2*ks][1],   ph[0], pl[0]);
                split2(s[2*ks][2],   s[2*ks][3],   ph[1], pl[1]);
                split2(s[2*ks+1][0], s[2*ks+1][1], ph[2], pl[2]);
                split2(s[2*ks+1][2], s[2*ks+1][3], ph[3], pl[3]);
#pragma unroll
                for (int p = 0; p < 4; p++) {
                    uint32_t off = (uint32_t)(p * 16) * 144 + (uint32_t)(ks * 16) * 2 + boff;
                    uint32_t h0, h1, h2, h3, e0, e1, e2, e3;
                    ldsm4(vhb + off, h0, h1, h2, h3);
                    ldsm4(vlb + off, e0, e1, e2, e3);
                    mma16816(o[2*p],   ph, h0, h1);
                    mma16816(o[2*p],   ph, e0, e1);
                    mma16816(o[2*p],   pl, h0, h1);
                    mma16816(o[2*p+1], ph, h2, h3);
                    mma16816(o[2*p+1], ph, e2, e3);
                    mma16816(o[2*p+1], pl, h2, h3);
                }
            }
            __syncthreads();   // all warps done before buffer reuse
        }

        // ---- finalize & store ----
        float inv0 = 1.f / l0s, inv1 = 1.f / l1s;
        int t0 = q0 + w16 + (lane >> 2);
        size_t rowb = ((size_t)b * NT + t0) * NH;
#pragma unroll
        for (int nf = 0; nf < 8; nf++) {
            int h = nf * 8 + ((lane & 3) << 1);
            float2 f0 = make_float2(o[nf][0] * inv0, o[nf][1] * inv0);
            float2 f1 = make_float2(o[nf][2] * inv1, o[nf][3] * inv1);
            *(float2*)&out[rowb + h]          = f0;
            *(float2*)&out[rowb + 8 * NH + h] = f1;
        }
        __syncthreads();
    }
}

// ===========================================================================
extern "C" void kernel_launch(void* const* d_in, const int* in_sizes, int n_in,
                              void* d_out, int out_size)
{
    (void)in_sizes; (void)n_in; (void)out_size;
    const float* x  = (const float*)d_in[0];
    const float* Wk = (const float*)d_in[1];
    const float* Wq = (const float*)d_in[2];
    const float* Wv = (const float*)d_in[3];
    float* out = (float*)d_out;

    cudaFuncSetAttribute(qkv_mma_kernel,
                         cudaFuncAttributeMaxDynamicSharedMemorySize, P_SMEM);
    cudaFuncSetAttribute(attn_mma_kernel,
                         cudaFuncAttributeMaxDynamicSharedMemorySize, A_SMEM);

    qkv_mma_kernel<<<NM / 128, 256, P_SMEM>>>(x, Wq, Wk, Wv);
    attn_mma_kernel<<<dim3(16, NB), 128, A_SMEM>>>(out);
}